// round 12
// baseline (speedup 1.0000x reference)
#include <cuda_runtime.h>
#include <cstdint>

// ---------------------------------------------------------------------------
// MaskAttention: B=2, S=3144, C=256, H=8, HD=32, QN=8, image 56x56, lepe 5x5 dw
// R10: R9 (split-K, fused QKV) with
//   - identity key order + k-slot<->key remapping absorbed into KsT reads:
//     mask via LDS.64, MMA2 B via LDS.64 from KsT (stride 72, conflict-free)
//   - finalize fused into lepe (image tokens); tiny finalize for query tokens
// softmax(qk + log(m+eps)) == (m+eps)*exp(qk) / sum_k (m+eps)*exp(qk)
// ---------------------------------------------------------------------------

#define B_   2
#define S_   3144
#define C_   256
#define H_   8
#define HD_  32
#define QN_  8
#define IMH_ 56
#define IMW_ 56
#define SCALE_ 0.17677669529663687f   // 32^-0.5

__device__ __align__(16) float g_q[B_*S_*C_];
__device__ __align__(16) float g_k[B_*S_*C_];
__device__ __align__(16) float g_v[B_*S_*C_];
__device__ __align__(16) float g_att[B_*S_*C_];
__device__ __align__(16) float g_on[2*B_*S_*C_];   // split partial numerators
__device__ __align__(16) float g_dn[2*B_*H_*S_];   // split partial denominators

// ----------------------------- helpers -------------------------------------
__device__ __forceinline__ uint32_t tf32r(float x) {
    uint32_t r;
    asm("cvt.rna.tf32.f32 %0, %1;" : "=r"(r) : "f"(x));
    return r;
}
__device__ __forceinline__ void mma_tf32(float* d, const uint32_t* a,
                                         uint32_t b0, uint32_t b1) {
    asm volatile(
        "mma.sync.aligned.m16n8k8.row.col.f32.tf32.tf32.f32 "
        "{%0,%1,%2,%3}, {%4,%5,%6,%7}, {%8,%9}, {%0,%1,%2,%3};"
        : "+f"(d[0]), "+f"(d[1]), "+f"(d[2]), "+f"(d[3])
        : "r"(a[0]), "r"(a[1]), "r"(a[2]), "r"(a[3]), "r"(b0), "r"(b1));
}
__device__ __forceinline__ float pexp(float s) {
    float p = fmaf(s, 1.f/24.f, 1.f/6.f);
    p = fmaf(p, s, 0.5f);
    p = fmaf(p, s, 1.f);
    return fmaf(p, s, 1.f);
}
__device__ __forceinline__ uint32_t smem_u32(const void* p) {
    uint32_t a;
    asm("{ .reg .u64 t; cvta.to.shared.u64 t, %1; cvt.u32.u64 %0, t; }"
        : "=r"(a) : "l"(p));
    return a;
}
#define CP_ASYNC16(dst, src, sz) \
    asm volatile("cp.async.ca.shared.global [%0], [%1], 16, %2;" \
                 :: "r"(dst), "l"(src), "r"(sz) : "memory")
#define CP_COMMIT() asm volatile("cp.async.commit_group;" ::: "memory")
#define CP_WAIT0()  asm volatile("cp.async.wait_group 0;" ::: "memory")

// ---------------------------------------------------------------------------
// Fused QKV projection: z selects (wq,bq)->g_q, (wk,bk)*SCALE->g_k, (wv,bv)->g_v
// ---------------------------------------------------------------------------
__global__ __launch_bounds__(256, 2) void qkv_gemm_kernel(
    const float* __restrict__ x,
    const float* __restrict__ wq, const float* __restrict__ bq,
    const float* __restrict__ wk, const float* __restrict__ bk,
    const float* __restrict__ wv, const float* __restrict__ bv)
{
    __shared__ float As[128][36];
    __shared__ float Ws[64][36];
    const int sel = blockIdx.z;
    const float* W    = (sel == 0) ? wq : (sel == 1) ? wk : wv;
    const float* bias = (sel == 0) ? bq : (sel == 1) ? bk : bv;
    float* Cm         = (sel == 0) ? g_q : (sel == 1) ? g_k : g_v;
    const float scale = (sel == 1) ? SCALE_ : 1.f;
    const int M = B_ * S_;

    const int m0 = blockIdx.x * 128, n0 = blockIdx.y * 64;
    const int t = threadIdx.x, w = t >> 5, lane = t & 31;
    const int g = lane >> 2, c = lane & 3;
    const int row0 = m0 + w * 16 + g, row1 = row0 + 8;

    float acc[8][4] = {};

    for (int k0 = 0; k0 < 256; k0 += 32) {
        __syncthreads();
        #pragma unroll
        for (int i = t; i < 1024; i += 256) {
            int r = i >> 3, sg = i & 7;
            int gm = m0 + r;
            float4 vv = make_float4(0.f, 0.f, 0.f, 0.f);
            if (gm < M) vv = *(const float4*)(x + (size_t)gm * 256 + k0 + sg * 4);
            uint4 u;
            u.x = tf32r(vv.x); u.y = tf32r(vv.y); u.z = tf32r(vv.z); u.w = tf32r(vv.w);
            *(uint4*)&As[r][sg * 4] = u;
        }
        #pragma unroll
        for (int i = t; i < 512; i += 256) {
            int r = i >> 3, sg = i & 7;
            float4 vv = *(const float4*)(W + (size_t)(n0 + r) * 256 + k0 + sg * 4);
            uint4 u;
            u.x = tf32r(vv.x); u.y = tf32r(vv.y); u.z = tf32r(vv.z); u.w = tf32r(vv.w);
            *(uint4*)&Ws[r][sg * 4] = u;
        }
        __syncthreads();

        #pragma unroll
        for (int ks = 0; ks < 4; ks++) {
            uint32_t a[4];
            a[0] = __float_as_uint(As[w*16 + g    ][ks*8 + c    ]);
            a[1] = __float_as_uint(As[w*16 + g + 8][ks*8 + c    ]);
            a[2] = __float_as_uint(As[w*16 + g    ][ks*8 + c + 4]);
            a[3] = __float_as_uint(As[w*16 + g + 8][ks*8 + c + 4]);
            #pragma unroll
            for (int nt = 0; nt < 8; nt++) {
                uint32_t b0 = __float_as_uint(Ws[nt*8 + g][ks*8 + c    ]);
                uint32_t b1 = __float_as_uint(Ws[nt*8 + g][ks*8 + c + 4]);
                mma_tf32(acc[nt], a, b0, b1);
            }
        }
    }

    #pragma unroll
    for (int nt = 0; nt < 8; nt++) {
        int n = n0 + nt * 8 + 2 * c;
        float2 bb = *(const float2*)(bias + n);
        if (row0 < M) {
            float2 r;
            r.x = (acc[nt][0] + bb.x) * scale;
            r.y = (acc[nt][1] + bb.y) * scale;
            *(float2*)(Cm + (size_t)row0 * 256 + n) = r;
        }
        if (row1 < M) {
            float2 r;
            r.x = (acc[nt][2] + bb.x) * scale;
            r.y = (acc[nt][3] + bb.y) * scale;
            *(float2*)(Cm + (size_t)row1 * 256 + n) = r;
        }
    }
}

// ---------------------------------------------------------------------------
// Output projection GEMM: out[M,256] = g_att @ wo^T + bo
// ---------------------------------------------------------------------------
__global__ __launch_bounds__(256, 2) void out_gemm_kernel(
    const float* __restrict__ W, const float* __restrict__ bias,
    float* __restrict__ Cext)
{
    __shared__ float As[128][36];
    __shared__ float Ws[64][36];
    const int M = B_ * S_;
    const int m0 = blockIdx.x * 128, n0 = blockIdx.y * 64;
    const int t = threadIdx.x, w = t >> 5, lane = t & 31;
    const int g = lane >> 2, c = lane & 3;
    const int row0 = m0 + w * 16 + g, row1 = row0 + 8;

    float acc[8][4] = {};

    for (int k0 = 0; k0 < 256; k0 += 32) {
        __syncthreads();
        #pragma unroll
        for (int i = t; i < 1024; i += 256) {
            int r = i >> 3, sg = i & 7;
            int gm = m0 + r;
            float4 vv = make_float4(0.f, 0.f, 0.f, 0.f);
            if (gm < M) vv = *(const float4*)(g_att + (size_t)gm * 256 + k0 + sg * 4);
            uint4 u;
            u.x = tf32r(vv.x); u.y = tf32r(vv.y); u.z = tf32r(vv.z); u.w = tf32r(vv.w);
            *(uint4*)&As[r][sg * 4] = u;
        }
        #pragma unroll
        for (int i = t; i < 512; i += 256) {
            int r = i >> 3, sg = i & 7;
            float4 vv = *(const float4*)(W + (size_t)(n0 + r) * 256 + k0 + sg * 4);
            uint4 u;
            u.x = tf32r(vv.x); u.y = tf32r(vv.y); u.z = tf32r(vv.z); u.w = tf32r(vv.w);
            *(uint4*)&Ws[r][sg * 4] = u;
        }
        __syncthreads();

        #pragma unroll
        for (int ks = 0; ks < 4; ks++) {
            uint32_t a[4];
            a[0] = __float_as_uint(As[w*16 + g    ][ks*8 + c    ]);
            a[1] = __float_as_uint(As[w*16 + g + 8][ks*8 + c    ]);
            a[2] = __float_as_uint(As[w*16 + g    ][ks*8 + c + 4]);
            a[3] = __float_as_uint(As[w*16 + g + 8][ks*8 + c + 4]);
            #pragma unroll
            for (int nt = 0; nt < 8; nt++) {
                uint32_t b0 = __float_as_uint(Ws[nt*8 + g][ks*8 + c    ]);
                uint32_t b1 = __float_as_uint(Ws[nt*8 + g][ks*8 + c + 4]);
                mma_tf32(acc[nt], a, b0, b1);
            }
        }
    }

    #pragma unroll
    for (int nt = 0; nt < 8; nt++) {
        int n = n0 + nt * 8 + 2 * c;
        float2 bb = *(const float2*)(bias + n);
        if (row0 < M) {
            float2 r;
            r.x = acc[nt][0] + bb.x;
            r.y = acc[nt][1] + bb.y;
            *(float2*)(Cext + (size_t)row0 * 256 + n) = r;
        }
        if (row1 < M) {
            float2 r;
            r.x = acc[nt][2] + bb.x;
            r.y = acc[nt][3] + bb.y;
            *(float2*)(Cext + (size_t)row1 * 256 + n) = r;
        }
    }
}

// ---------------------------------------------------------------------------
// Attention (split-K). CTA = 128 queries x 1 head x 25 key tiles.
// grid (25, 8, B*2): z = b*2 + split. Writes unnormalized partials.
// Smem (float indices):
//   Ks [2][64][36] @ 0     (K [key][dim], MMA1 B, LDS.32 pairs conflict-free)
//   KsT[2][32][72] @ 4608  (K [dim][key] stride 72, MMA2 B, LDS.64 conflict-free)
//   Ms [2][8][16][68] @ 9216 (mask tiles, cp.async)
// total = (9216 + 17408)*4 = 106496 bytes -> 2 CTAs/SM
// Identity key order; A-frag k-slot c <-> key 2c, k-slot c+4 <-> key 2c+1,
// matched by KsT/mask adjacent-pair reads. C-frag == A-frag up to renaming.
// ---------------------------------------------------------------------------
#define KST_F   4608
#define MSK_F   9216
#define MSK_BUF 8704
#define SMEM_ATTN 106496
#define SPLIT_T  25

__global__ __launch_bounds__(256, 2) void attn_mma_kernel(const float* __restrict__ maskp)
{
    extern __shared__ __align__(16) float ds[];

    const int q0 = blockIdx.x * 128;
    const int h  = blockIdx.y;
    const int b  = blockIdx.z >> 1;
    const int split = blockIdx.z & 1;
    const int kt0 = split * SPLIT_T, kt1 = kt0 + SPLIT_T;
    const int t = threadIdx.x, w = t >> 5, lane = t & 31;
    const int g = lane >> 2, c = lane & 3;
    const int row0 = q0 + w * 16 + g, row1 = row0 + 8;
    const bool v0 = row0 < S_, v1 = row1 < S_;

    const float* qb = g_q + (size_t)b * S_ * C_ + h * HD_;
    const float* kb = g_k + (size_t)b * S_ * C_ + h * HD_;
    const float* mb = maskp + (size_t)b * S_ * S_;

    // Q fragments (persist)
    uint32_t qa[4][4];
    #pragma unroll
    for (int ks = 0; ks < 4; ks++) {
        int d0 = ks * 8 + c;
        qa[ks][0] = v0 ? tf32r(qb[(size_t)row0 * C_ + d0    ]) : 0u;
        qa[ks][1] = v1 ? tf32r(qb[(size_t)row1 * C_ + d0    ]) : 0u;
        qa[ks][2] = v0 ? tf32r(qb[(size_t)row0 * C_ + d0 + 4]) : 0u;
        qa[ks][3] = v1 ? tf32r(qb[(size_t)row1 * C_ + d0 + 4]) : 0u;
    }

    const int kr0 = t >> 3, ksg = t & 7;
    const int kr1 = kr0 + 32;

    uint32_t msmem[8];
    {
        uint32_t base = smem_u32(ds + MSK_F);
        #pragma unroll
        for (int jj = 0; jj < 8; jj++) {
            int j = jj * 32 + lane;
            int row = j >> 4, col4 = j & 15;
            msmem[jj] = base + (uint32_t)(((w * 16 + row) * 68 + col4 * 4) * 4);
        }
    }
    const uint32_t msbuf_bytes = MSK_BUF * 4u;

    // issue mask(kt0) prefetch into buffer (kt0 & 1)
    {
        uint32_t boff = (uint32_t)(kt0 & 1) * msbuf_bytes;
        #pragma unroll
        for (int jj = 0; jj < 8; jj++) {
            int j = jj * 32 + lane;
            int row = j >> 4, col4 = j & 15;
            int grow = q0 + w * 16 + row;
            int gcol = kt0 * 64 + col4 * 4;
            uint32_t sz = (grow < S_) ? 16u : 0u;
            const float* src = mb + (size_t)(sz ? grow : 0) * S_ + gcol;
            CP_ASYNC16(msmem[jj] + boff, src, sz);
        }
        CP_COMMIT();
    }

    // ---- load K tile kt0 into Ks/KsT buffer (kt0 & 1); rows all < S_ ----
    {
        const int base = kt0 * 64;
        float* Ks0  = ds + (kt0 & 1) * 2304;
        float* KsT0 = ds + KST_F + (kt0 & 1) * 2304;
        float4 a0 = *(const float4*)(kb + (size_t)(base + kr0) * C_ + ksg * 4);
        float4 a1 = *(const float4*)(kb + (size_t)(base + kr1) * C_ + ksg * 4);
        uint4 u;
        u.x = tf32r(a0.x); u.y = tf32r(a0.y); u.z = tf32r(a0.z); u.w = tf32r(a0.w);
        *(uint4*)&Ks0[kr0 * 36 + ksg * 4] = u;
        KsT0[(ksg*4 + 0) * 72 + kr0] = __uint_as_float(u.x);
        KsT0[(ksg*4 + 1) * 72 + kr0] = __uint_as_float(u.y);
        KsT0[(ksg*4 + 2) * 72 + kr0] = __uint_as_float(u.z);
        KsT0[(ksg*4 + 3) * 72 + kr0] = __uint_as_float(u.w);
        u.x = tf32r(a1.x); u.y = tf32r(a1.y); u.z = tf32r(a1.z); u.w = tf32r(a1.w);
        *(uint4*)&Ks0[kr1 * 36 + ksg * 4] = u;
        KsT0[(ksg*4 + 0) * 72 + kr1] = __uint_as_float(u.x);
        KsT0[(ksg*4 + 1) * 72 + kr1] = __uint_as_float(u.y);
        KsT0[(ksg*4 + 2) * 72 + kr1] = __uint_as_float(u.z);
        KsT0[(ksg*4 + 3) * 72 + kr1] = __uint_as_float(u.w);
    }

    float o[4][4] = {};
    float den0 = 0.f, den1 = 0.f;

    for (int kt = kt0; kt < kt1; kt++) {
        const int k0 = kt * 64;
        const int cur = kt & 1;
        CP_WAIT0();
        __syncthreads();

        // ---- prefetch next tile ----
        float4 nk0v, nk1v;
        if (kt < kt1 - 1) {
            const int nk0 = k0 + 64;
            uint32_t boff = (uint32_t)(cur ^ 1) * msbuf_bytes;
            #pragma unroll
            for (int jj = 0; jj < 8; jj++) {
                int j = jj * 32 + lane;
                int row = j >> 4, col4 = j & 15;
                int grow = q0 + w * 16 + row;
                int gcol = nk0 + col4 * 4;
                uint32_t sz = (grow < S_ && gcol < S_) ? 16u : 0u;
                const float* src = mb + (size_t)(sz ? grow : 0) * S_ + (sz ? gcol : 0);
                CP_ASYNC16(msmem[jj] + boff, src, sz);
            }
            CP_COMMIT();
            int gk0 = nk0 + kr0, gk1 = nk0 + kr1;
            nk0v = make_float4(0.f, 0.f, 0.f, 0.f);
            nk1v = nk0v;
            if (gk0 < S_) nk0v = *(const float4*)(kb + (size_t)gk0 * C_ + ksg * 4);
            if (gk1 < S_) nk1v = *(const float4*)(kb + (size_t)gk1 * C_ + ksg * 4);
        }

        const float* Ksc  = ds + cur * 2304;
        const float* KsTc = ds + KST_F + cur * 2304;
        const float* Msc  = ds + MSK_F + (size_t)cur * MSK_BUF + (size_t)w * 16 * 68;

        #pragma unroll
        for (int nt = 0; nt < 8; nt++) {
            // MMA1, identity key order: S col j holds key j
            float s[4] = {0.f, 0.f, 0.f, 0.f};
            #pragma unroll
            for (int ks = 0; ks < 4; ks++) {
                uint32_t b0 = __float_as_uint(Ksc[(nt*8 + g) * 36 + ks*8 + c    ]);
                uint32_t b1 = __float_as_uint(Ksc[(nt*8 + g) * 36 + ks*8 + c + 4]);
                mma_tf32(s, qa[ks], b0, b1);
            }
            // s[0]=row0/key 2c, s[1]=row0/key 2c+1, s[2]=row1/key 2c, s[3]=row1/key 2c+1
            const bool kv = (k0 + nt * 8) < S_;
            float w00 = 0.f, w01 = 0.f, w02 = 0.f, w03 = 0.f;
            if (kv) {
                if (v0) {
                    float2 mm = *(const float2*)&Msc[g * 68 + nt*8 + 2*c];
                    w00 = (mm.x + 1e-6f) * pexp(s[0]);
                    w01 = (mm.y + 1e-6f) * pexp(s[1]);
                }
                if (v1) {
                    float2 mm = *(const float2*)&Msc[(g + 8) * 68 + nt*8 + 2*c];
                    w02 = (mm.x + 1e-6f) * pexp(s[2]);
                    w03 = (mm.y + 1e-6f) * pexp(s[3]);
                }
            }
            den0 += w00 + w01;
            den1 += w02 + w03;

            // A-frag: k-slot c <-> key 2c, k-slot c+4 <-> key 2c+1
            uint32_t a[4];
            a[0] = tf32r(w00);
            a[1] = tf32r(w02);
            a[2] = tf32r(w01);
            a[3] = tf32r(w03);

            // MMA2 B: adjacent key pair (2c, 2c+1) -> single LDS.64 from KsT
            #pragma unroll
            for (int nt2 = 0; nt2 < 4; nt2++) {
                float2 bb = *(const float2*)&KsTc[(nt2*8 + g) * 72 + nt*8 + 2*c];
                mma_tf32(o[nt2], a, __float_as_uint(bb.x), __float_as_uint(bb.y));
            }
        }

        if (kt < kt1 - 1) {
            float* Ksn  = ds + (cur ^ 1) * 2304;
            float* KsTn = ds + KST_F + (cur ^ 1) * 2304;
            uint4 u;
            u.x = tf32r(nk0v.x); u.y = tf32r(nk0v.y); u.z = tf32r(nk0v.z); u.w = tf32r(nk0v.w);
            *(uint4*)&Ksn[kr0 * 36 + ksg * 4] = u;
            KsTn[(ksg*4 + 0) * 72 + kr0] = __uint_as_float(u.x);
            KsTn[(ksg*4 + 1) * 72 + kr0] = __uint_as_float(u.y);
            KsTn[(ksg*4 + 2) * 72 + kr0] = __uint_as_float(u.z);
            KsTn[(ksg*4 + 3) * 72 + kr0] = __uint_as_float(u.w);
            u.x = tf32r(nk1v.x); u.y = tf32r(nk1v.y); u.z = tf32r(nk1v.z); u.w = tf32r(nk1v.w);
            *(uint4*)&Ksn[kr1 * 36 + ksg * 4] = u;
            KsTn[(ksg*4 + 0) * 72 + kr1] = __uint_as_float(u.x);
            KsTn[(ksg*4 + 1) * 72 + kr1] = __uint_as_float(u.y);
            KsTn[(ksg*4 + 2) * 72 + kr1] = __uint_as_float(u.z);
            KsTn[(ksg*4 + 3) * 72 + kr1] = __uint_as_float(u.w);
        }
    }

    // quad-reduce denominators
    den0 += __shfl_xor_sync(0xffffffffu, den0, 1);
    den0 += __shfl_xor_sync(0xffffffffu, den0, 2);
    den1 += __shfl_xor_sync(0xffffffffu, den1, 1);
    den1 += __shfl_xor_sync(0xffffffffu, den1, 2);

    // ---- write unnormalized partials ----
    float* on = g_on + (size_t)split * B_ * S_ * C_;
    float* ob0 = on + ((size_t)b * S_ + row0) * C_ + h * HD_;
    float* ob1 = on + ((size_t)b * S_ + row1) * C_ + h * HD_;
    #pragma unroll
    for (int nt2 = 0; nt2 < 4; nt2++) {
        if (v0) {
            float2 r; r.x = o[nt2][0]; r.y = o[nt2][1];
            *(float2*)(ob0 + nt2 * 8 + 2 * c) = r;
        }
        if (v1) {
            float2 r; r.x = o[nt2][2]; r.y = o[nt2][3];
            *(float2*)(ob1 + nt2 * 8 + 2 * c) = r;
        }
    }
    if (c == 0) {
        float* dn = g_dn + (size_t)split * B_ * H_ * S_ + ((size_t)b * H_ + h) * S_;
        if (v0) dn[row0] = den0;
        if (v1) dn[row1] = den1;
    }
}

// ---------------------------------------------------------------------------
// Finalize for query tokens (s < QN): g_att = (O0+O1)/(d0+d1)
// ---------------------------------------------------------------------------
__global__ __launch_bounds__(256) void finalize_q_kernel()
{
    const int s = blockIdx.x, b = blockIdx.y, c = threadIdx.x;
    const int h = c >> 5;
    const size_t di = ((size_t)b * H_ + h) * S_ + s;
    const float den = g_dn[di] + g_dn[(size_t)B_ * H_ * S_ + di];
    const size_t oi = ((size_t)b * S_ + s) * C_ + c;
    g_att[oi] = (g_on[oi] + g_on[(size_t)B_ * S_ * C_ + oi]) / den;
}

// ---------------------------------------------------------------------------
// Fused finalize + LEPE for image tokens (s >= QN):
// g_att = (O0+O1)/(d0+d1) + dwconv5x5(v) + lepe_bias
// ---------------------------------------------------------------------------
__global__ __launch_bounds__(256) void lepe_fin_kernel(
    const float* __restrict__ lw, const float* __restrict__ lb)
{
    __shared__ float dsh[8];
    const int p = blockIdx.x;            // 0..3135
    const int b = blockIdx.y;
    const int c = threadIdx.x;
    const int s = QN_ + p;

    if (c < 8) {
        const size_t di = ((size_t)b * H_ + c) * S_ + s;
        dsh[c] = g_dn[di] + g_dn[(size_t)B_ * H_ * S_ + di];
    }
    __syncthreads();

    const size_t oi = ((size_t)b * S_ + s) * C_ + c;
    const float fin = (g_on[oi] + g_on[(size_t)B_ * S_ * C_ + oi]) / dsh[c >> 5];

    const int i = p / IMW_, j = p % IMW_;
    float acc = lb[c];
    #pragma unroll
    for (int u = 0; u < 5; u++) {
        const int ii = i + u - 2;
        if ((unsigned)ii >= IMH_) continue;
        const float* vrow = g_v + ((size_t)b * S_ + QN_ + ii * IMW_ + j - 2) * C_ + c;
        const float* wrow = lw + (u * 5) * C_ + c;
        #pragma unroll
        for (int v = 0; v < 5; v++) {
            const int jj = j + v - 2;
            if ((unsigned)jj < IMW_)
                acc += vrow[(size_t)v * C_] * wrow[(size_t)v * C_];
        }
    }
    g_att[oi] = fin + acc;
}

// ---------------------------------------------------------------------------
extern "C" void kernel_launch(void* const* d_in, const int* in_sizes, int n_in,
                              void* d_out, int out_size)
{
    const float* x    = (const float*)d_in[0];
    const float* mask = (const float*)d_in[1];
    const float* wq   = (const float*)d_in[2];
    const float* bq   = (const float*)d_in[3];
    const float* wk   = (const float*)d_in[4];
    const float* bk   = (const float*)d_in[5];
    const float* wv   = (const float*)d_in[6];
    const float* bv   = (const float*)d_in[7];
    const float* lw   = (const float*)d_in[8];
    const float* lb   = (const float*)d_in[9];
    const float* wo   = (const float*)d_in[10];
    const float* bo   = (const float*)d_in[11];
    float* out = (float*)d_out;

    const int M = B_ * S_;                       // 6288
    dim3 gqkv((M + 127) / 128, C_ / 64, 3);      // 50 x 4 x 3
    dim3 go((M + 127) / 128, C_ / 64);           // 50 x 4

    static int smem_set = 0;
    if (!smem_set) {
        cudaFuncSetAttribute(attn_mma_kernel,
                             cudaFuncAttributeMaxDynamicSharedMemorySize, SMEM_ATTN);
        smem_set = 1;
    }

    qkv_gemm_kernel<<<gqkv, 256>>>(x, wq, bq, wk, bk, wv, bv);

    attn_mma_kernel<<<dim3((S_ + 127) / 128, H_, B_ * 2), 256, SMEM_ATTN>>>(mask);

    finalize_q_kernel<<<dim3(QN_, B_), 256>>>();
    lepe_fin_kernel<<<dim3(IMH_ * IMW_, B_), 256>>>(lw, lb);

    out_gemm_kernel<<<go, 256>>>(wo, bo, out);
}

// round 14
// speedup vs baseline: 1.0501x; 1.0501x over previous
#include <cuda_runtime.h>
#include <cstdint>

// ---------------------------------------------------------------------------
// MaskAttention: B=2, S=3144, C=256, H=8, HD=32, QN=8, image 56x56, lepe 5x5 dw
// R13: R9 attention kernel verbatim (measured best) + R12's validated
//      lepe+finalize fusion (image tokens) and finalize_q (query tokens).
// softmax(qk + log(m+eps)) == (m+eps)*exp(qk) / sum_k (m+eps)*exp(qk)
// ---------------------------------------------------------------------------

#define B_   2
#define S_   3144
#define C_   256
#define H_   8
#define HD_  32
#define QN_  8
#define IMH_ 56
#define IMW_ 56
#define SCALE_ 0.17677669529663687f   // 32^-0.5

__device__ __align__(16) float g_q[B_*S_*C_];
__device__ __align__(16) float g_k[B_*S_*C_];
__device__ __align__(16) float g_v[B_*S_*C_];
__device__ __align__(16) float g_att[B_*S_*C_];
__device__ __align__(16) float g_on[2*B_*S_*C_];   // split partial numerators
__device__ __align__(16) float g_dn[2*B_*H_*S_];   // split partial denominators

// ----------------------------- helpers -------------------------------------
__device__ __forceinline__ uint32_t tf32r(float x) {
    uint32_t r;
    asm("cvt.rna.tf32.f32 %0, %1;" : "=r"(r) : "f"(x));
    return r;
}
__device__ __forceinline__ void mma_tf32(float* d, const uint32_t* a,
                                         uint32_t b0, uint32_t b1) {
    asm volatile(
        "mma.sync.aligned.m16n8k8.row.col.f32.tf32.tf32.f32 "
        "{%0,%1,%2,%3}, {%4,%5,%6,%7}, {%8,%9}, {%0,%1,%2,%3};"
        : "+f"(d[0]), "+f"(d[1]), "+f"(d[2]), "+f"(d[3])
        : "r"(a[0]), "r"(a[1]), "r"(a[2]), "r"(a[3]), "r"(b0), "r"(b1));
}
__device__ __forceinline__ float pexp(float s) {
    float p = fmaf(s, 1.f/24.f, 1.f/6.f);
    p = fmaf(p, s, 0.5f);
    p = fmaf(p, s, 1.f);
    return fmaf(p, s, 1.f);
}
__device__ __forceinline__ uint32_t smem_u32(const void* p) {
    uint32_t a;
    asm("{ .reg .u64 t; cvta.to.shared.u64 t, %1; cvt.u32.u64 %0, t; }"
        : "=r"(a) : "l"(p));
    return a;
}
#define CP_ASYNC16(dst, src, sz) \
    asm volatile("cp.async.ca.shared.global [%0], [%1], 16, %2;" \
                 :: "r"(dst), "l"(src), "r"(sz) : "memory")
#define CP_COMMIT() asm volatile("cp.async.commit_group;" ::: "memory")
#define CP_WAIT0()  asm volatile("cp.async.wait_group 0;" ::: "memory")

// ---------------------------------------------------------------------------
// Fused QKV projection: z selects (wq,bq)->g_q, (wk,bk)*SCALE->g_k, (wv,bv)->g_v
// ---------------------------------------------------------------------------
__global__ __launch_bounds__(256, 2) void qkv_gemm_kernel(
    const float* __restrict__ x,
    const float* __restrict__ wq, const float* __restrict__ bq,
    const float* __restrict__ wk, const float* __restrict__ bk,
    const float* __restrict__ wv, const float* __restrict__ bv)
{
    __shared__ float As[128][36];
    __shared__ float Ws[64][36];
    const int sel = blockIdx.z;
    const float* W    = (sel == 0) ? wq : (sel == 1) ? wk : wv;
    const float* bias = (sel == 0) ? bq : (sel == 1) ? bk : bv;
    float* Cm         = (sel == 0) ? g_q : (sel == 1) ? g_k : g_v;
    const float scale = (sel == 1) ? SCALE_ : 1.f;
    const int M = B_ * S_;

    const int m0 = blockIdx.x * 128, n0 = blockIdx.y * 64;
    const int t = threadIdx.x, w = t >> 5, lane = t & 31;
    const int g = lane >> 2, c = lane & 3;
    const int row0 = m0 + w * 16 + g, row1 = row0 + 8;

    float acc[8][4] = {};

    for (int k0 = 0; k0 < 256; k0 += 32) {
        __syncthreads();
        #pragma unroll
        for (int i = t; i < 1024; i += 256) {
            int r = i >> 3, sg = i & 7;
            int gm = m0 + r;
            float4 vv = make_float4(0.f, 0.f, 0.f, 0.f);
            if (gm < M) vv = *(const float4*)(x + (size_t)gm * 256 + k0 + sg * 4);
            uint4 u;
            u.x = tf32r(vv.x); u.y = tf32r(vv.y); u.z = tf32r(vv.z); u.w = tf32r(vv.w);
            *(uint4*)&As[r][sg * 4] = u;
        }
        #pragma unroll
        for (int i = t; i < 512; i += 256) {
            int r = i >> 3, sg = i & 7;
            float4 vv = *(const float4*)(W + (size_t)(n0 + r) * 256 + k0 + sg * 4);
            uint4 u;
            u.x = tf32r(vv.x); u.y = tf32r(vv.y); u.z = tf32r(vv.z); u.w = tf32r(vv.w);
            *(uint4*)&Ws[r][sg * 4] = u;
        }
        __syncthreads();

        #pragma unroll
        for (int ks = 0; ks < 4; ks++) {
            uint32_t a[4];
            a[0] = __float_as_uint(As[w*16 + g    ][ks*8 + c    ]);
            a[1] = __float_as_uint(As[w*16 + g + 8][ks*8 + c    ]);
            a[2] = __float_as_uint(As[w*16 + g    ][ks*8 + c + 4]);
            a[3] = __float_as_uint(As[w*16 + g + 8][ks*8 + c + 4]);
            #pragma unroll
            for (int nt = 0; nt < 8; nt++) {
                uint32_t b0 = __float_as_uint(Ws[nt*8 + g][ks*8 + c    ]);
                uint32_t b1 = __float_as_uint(Ws[nt*8 + g][ks*8 + c + 4]);
                mma_tf32(acc[nt], a, b0, b1);
            }
        }
    }

    #pragma unroll
    for (int nt = 0; nt < 8; nt++) {
        int n = n0 + nt * 8 + 2 * c;
        float2 bb = *(const float2*)(bias + n);
        if (row0 < M) {
            float2 r;
            r.x = (acc[nt][0] + bb.x) * scale;
            r.y = (acc[nt][1] + bb.y) * scale;
            *(float2*)(Cm + (size_t)row0 * 256 + n) = r;
        }
        if (row1 < M) {
            float2 r;
            r.x = (acc[nt][2] + bb.x) * scale;
            r.y = (acc[nt][3] + bb.y) * scale;
            *(float2*)(Cm + (size_t)row1 * 256 + n) = r;
        }
    }
}

// ---------------------------------------------------------------------------
// Output projection GEMM: out[M,256] = g_att @ wo^T + bo
// ---------------------------------------------------------------------------
__global__ __launch_bounds__(256, 2) void out_gemm_kernel(
    const float* __restrict__ W, const float* __restrict__ bias,
    float* __restrict__ Cext)
{
    __shared__ float As[128][36];
    __shared__ float Ws[64][36];
    const int M = B_ * S_;
    const int m0 = blockIdx.x * 128, n0 = blockIdx.y * 64;
    const int t = threadIdx.x, w = t >> 5, lane = t & 31;
    const int g = lane >> 2, c = lane & 3;
    const int row0 = m0 + w * 16 + g, row1 = row0 + 8;

    float acc[8][4] = {};

    for (int k0 = 0; k0 < 256; k0 += 32) {
        __syncthreads();
        #pragma unroll
        for (int i = t; i < 1024; i += 256) {
            int r = i >> 3, sg = i & 7;
            int gm = m0 + r;
            float4 vv = make_float4(0.f, 0.f, 0.f, 0.f);
            if (gm < M) vv = *(const float4*)(g_att + (size_t)gm * 256 + k0 + sg * 4);
            uint4 u;
            u.x = tf32r(vv.x); u.y = tf32r(vv.y); u.z = tf32r(vv.z); u.w = tf32r(vv.w);
            *(uint4*)&As[r][sg * 4] = u;
        }
        #pragma unroll
        for (int i = t; i < 512; i += 256) {
            int r = i >> 3, sg = i & 7;
            float4 vv = *(const float4*)(W + (size_t)(n0 + r) * 256 + k0 + sg * 4);
            uint4 u;
            u.x = tf32r(vv.x); u.y = tf32r(vv.y); u.z = tf32r(vv.z); u.w = tf32r(vv.w);
            *(uint4*)&Ws[r][sg * 4] = u;
        }
        __syncthreads();

        #pragma unroll
        for (int ks = 0; ks < 4; ks++) {
            uint32_t a[4];
            a[0] = __float_as_uint(As[w*16 + g    ][ks*8 + c    ]);
            a[1] = __float_as_uint(As[w*16 + g + 8][ks*8 + c    ]);
            a[2] = __float_as_uint(As[w*16 + g    ][ks*8 + c + 4]);
            a[3] = __float_as_uint(As[w*16 + g + 8][ks*8 + c + 4]);
            #pragma unroll
            for (int nt = 0; nt < 8; nt++) {
                uint32_t b0 = __float_as_uint(Ws[nt*8 + g][ks*8 + c    ]);
                uint32_t b1 = __float_as_uint(Ws[nt*8 + g][ks*8 + c + 4]);
                mma_tf32(acc[nt], a, b0, b1);
            }
        }
    }

    #pragma unroll
    for (int nt = 0; nt < 8; nt++) {
        int n = n0 + nt * 8 + 2 * c;
        float2 bb = *(const float2*)(bias + n);
        if (row0 < M) {
            float2 r;
            r.x = acc[nt][0] + bb.x;
            r.y = acc[nt][1] + bb.y;
            *(float2*)(Cext + (size_t)row0 * 256 + n) = r;
        }
        if (row1 < M) {
            float2 r;
            r.x = acc[nt][2] + bb.x;
            r.y = acc[nt][3] + bb.y;
            *(float2*)(Cext + (size_t)row1 * 256 + n) = r;
        }
    }
}

// ---------------------------------------------------------------------------
// Attention (split-K) — R9 version verbatim.
// CTA = 128 queries x 1 head x 25 key tiles. grid (25, 8, B*2).
// Smem: Ks[2][64][36] @0, KsT[2][32][68] @4608, Ms[2][8][16][68] @8960.
// Key-group permutation p = {0,4,1,5,2,6,3,7} makes C-frag == A-frag.
// ---------------------------------------------------------------------------
#define KST_F   4608
#define MSK_F   8960
#define MSK_BUF 8704
#define SMEM_ATTN 105472
#define SPLIT_T  25

__global__ __launch_bounds__(256, 2) void attn_mma_kernel(const float* __restrict__ maskp)
{
    extern __shared__ __align__(16) float ds[];

    const int q0 = blockIdx.x * 128;
    const int h  = blockIdx.y;
    const int b  = blockIdx.z >> 1;
    const int split = blockIdx.z & 1;
    const int kt0 = split * SPLIT_T, kt1 = kt0 + SPLIT_T;
    const int t = threadIdx.x, w = t >> 5, lane = t & 31;
    const int g = lane >> 2, c = lane & 3;
    const int pg = (g >> 1) + (g & 1) * 4;     // key-group permutation p(g)
    const int row0 = q0 + w * 16 + g, row1 = row0 + 8;
    const bool v0 = row0 < S_, v1 = row1 < S_;

    const float* qb = g_q + (size_t)b * S_ * C_ + h * HD_;
    const float* kb = g_k + (size_t)b * S_ * C_ + h * HD_;
    const float* mb = maskp + (size_t)b * S_ * S_;

    // Q fragments (persist)
    uint32_t qa[4][4];
    #pragma unroll
    for (int ks = 0; ks < 4; ks++) {
        int d0 = ks * 8 + c;
        qa[ks][0] = v0 ? tf32r(qb[(size_t)row0 * C_ + d0    ]) : 0u;
        qa[ks][1] = v1 ? tf32r(qb[(size_t)row1 * C_ + d0    ]) : 0u;
        qa[ks][2] = v0 ? tf32r(qb[(size_t)row0 * C_ + d0 + 4]) : 0u;
        qa[ks][3] = v1 ? tf32r(qb[(size_t)row1 * C_ + d0 + 4]) : 0u;
    }

    const int kr0 = t >> 3, ksg = t & 7;
    const int kr1 = kr0 + 32;

    uint32_t msmem[8];
    {
        uint32_t base = smem_u32(ds + MSK_F);
        #pragma unroll
        for (int jj = 0; jj < 8; jj++) {
            int j = jj * 32 + lane;
            int row = j >> 4, col4 = j & 15;
            msmem[jj] = base + (uint32_t)(((w * 16 + row) * 68 + col4 * 4) * 4);
        }
    }
    const uint32_t msbuf_bytes = MSK_BUF * 4u;

    // issue mask(kt0) prefetch into buffer (kt0 & 1)
    {
        uint32_t boff = (uint32_t)(kt0 & 1) * msbuf_bytes;
        #pragma unroll
        for (int jj = 0; jj < 8; jj++) {
            int j = jj * 32 + lane;
            int row = j >> 4, col4 = j & 15;
            int grow = q0 + w * 16 + row;
            int gcol = kt0 * 64 + col4 * 4;
            uint32_t sz = (grow < S_) ? 16u : 0u;
            const float* src = mb + (size_t)(sz ? grow : 0) * S_ + gcol;
            CP_ASYNC16(msmem[jj] + boff, src, sz);
        }
        CP_COMMIT();
    }

    // ---- load K tile kt0 into Ks/KsT buffer (kt0 & 1); rows all < S_ ----
    {
        const int base = kt0 * 64;
        float* Ks0  = ds + (kt0 & 1) * 2304;
        float* KsT0 = ds + KST_F + (kt0 & 1) * 2176;
        float4 a0 = *(const float4*)(kb + (size_t)(base + kr0) * C_ + ksg * 4);
        float4 a1 = *(const float4*)(kb + (size_t)(base + kr1) * C_ + ksg * 4);
        uint4 u;
        u.x = tf32r(a0.x); u.y = tf32r(a0.y); u.z = tf32r(a0.z); u.w = tf32r(a0.w);
        *(uint4*)&Ks0[kr0 * 36 + ksg * 4] = u;
        KsT0[(ksg*4 + 0) * 68 + kr0] = __uint_as_float(u.x);
        KsT0[(ksg*4 + 1) * 68 + kr0] = __uint_as_float(u.y);
        KsT0[(ksg*4 + 2) * 68 + kr0] = __uint_as_float(u.z);
        KsT0[(ksg*4 + 3) * 68 + kr0] = __uint_as_float(u.w);
        u.x = tf32r(a1.x); u.y = tf32r(a1.y); u.z = tf32r(a1.z); u.w = tf32r(a1.w);
        *(uint4*)&Ks0[kr1 * 36 + ksg * 4] = u;
        KsT0[(ksg*4 + 0) * 68 + kr1] = __uint_as_float(u.x);
        KsT0[(ksg*4 + 1) * 68 + kr1] = __uint_as_float(u.y);
        KsT0[(ksg*4 + 2) * 68 + kr1] = __uint_as_float(u.z);
        KsT0[(ksg*4 + 3) * 68 + kr1] = __uint_as_float(u.w);
    }

    float o[4][4] = {};
    float den0 = 0.f, den1 = 0.f;

    for (int kt = kt0; kt < kt1; kt++) {
        const int k0 = kt * 64;
        const int cur = kt & 1;
        CP_WAIT0();
        __syncthreads();

        // ---- prefetch next tile ----
        float4 nk0v, nk1v;
        if (kt < kt1 - 1) {
            const int nk0 = k0 + 64;
            uint32_t boff = (uint32_t)(cur ^ 1) * msbuf_bytes;
            #pragma unroll
            for (int jj = 0; jj < 8; jj++) {
                int j = jj * 32 + lane;
                int row = j >> 4, col4 = j & 15;
                int grow = q0 + w * 16 + row;
                int gcol = nk0 + col4 * 4;
                uint32_t sz = (grow < S_ && gcol < S_) ? 16u : 0u;
                const float* src = mb + (size_t)(sz ? grow : 0) * S_ + (sz ? gcol : 0);
                CP_ASYNC16(msmem[jj] + boff, src, sz);
            }
            CP_COMMIT();
            int gk0 = nk0 + kr0, gk1 = nk0 + kr1;
            nk0v = make_float4(0.f, 0.f, 0.f, 0.f);
            nk1v = nk0v;
            if (gk0 < S_) nk0v = *(const float4*)(kb + (size_t)gk0 * C_ + ksg * 4);
            if (gk1 < S_) nk1v = *(const float4*)(kb + (size_t)gk1 * C_ + ksg * 4);
        }

        const float* Ksc  = ds + cur * 2304;
        const float* KsTc = ds + KST_F + cur * 2176;
        const float* Msc  = ds + MSK_F + (size_t)cur * MSK_BUF + (size_t)w * 16 * 68;

        #pragma unroll
        for (int nt = 0; nt < 8; nt++) {
            float s[4] = {0.f, 0.f, 0.f, 0.f};
            #pragma unroll
            for (int ks = 0; ks < 4; ks++) {
                uint32_t b0 = __float_as_uint(Ksc[(nt*8 + pg) * 36 + ks*8 + c    ]);
                uint32_t b1 = __float_as_uint(Ksc[(nt*8 + pg) * 36 + ks*8 + c + 4]);
                mma_tf32(s, qa[ks], b0, b1);
            }
            const bool kv = (k0 + nt * 8) < S_;
            float w00 = 0.f, w01 = 0.f, w02 = 0.f, w03 = 0.f;
            if (kv) {
                if (v0) {
                    float ma  = Msc[g * 68 + nt*8 + c    ];
                    float mbv = Msc[g * 68 + nt*8 + c + 4];
                    w00 = (ma  + 1e-6f) * pexp(s[0]);
                    w01 = (mbv + 1e-6f) * pexp(s[1]);
                }
                if (v1) {
                    float ma  = Msc[(g + 8) * 68 + nt*8 + c    ];
                    float mbv = Msc[(g + 8) * 68 + nt*8 + c + 4];
                    w02 = (ma  + 1e-6f) * pexp(s[2]);
                    w03 = (mbv + 1e-6f) * pexp(s[3]);
                }
            }
            den0 += w00 + w01;
            den1 += w02 + w03;

            uint32_t a[4];
            a[0] = tf32r(w00);
            a[1] = tf32r(w02);
            a[2] = tf32r(w01);
            a[3] = tf32r(w03);

            #pragma unroll
            for (int nt2 = 0; nt2 < 4; nt2++) {
                uint32_t b0 = __float_as_uint(KsTc[(nt2*8 + g) * 68 + nt*8 + c    ]);
                uint32_t b1 = __float_as_uint(KsTc[(nt2*8 + g) * 68 + nt*8 + c + 4]);
                mma_tf32(o[nt2], a, b0, b1);
            }
        }

        if (kt < kt1 - 1) {
            float* Ksn  = ds + (cur ^ 1) * 2304;
            float* KsTn = ds + KST_F + (cur ^ 1) * 2176;
            uint4 u;
            u.x = tf32r(nk0v.x); u.y = tf32r(nk0v.y); u.z = tf32r(nk0v.z); u.w = tf32r(nk0v.w);
            *(uint4*)&Ksn[kr0 * 36 + ksg * 4] = u;
            KsTn[(ksg*4 + 0) * 68 + kr0] = __uint_as_float(u.x);
            KsTn[(ksg*4 + 1) * 68 + kr0] = __uint_as_float(u.y);
            KsTn[(ksg*4 + 2) * 68 + kr0] = __uint_as_float(u.z);
            KsTn[(ksg*4 + 3) * 68 + kr0] = __uint_as_float(u.w);
            u.x = tf32r(nk1v.x); u.y = tf32r(nk1v.y); u.z = tf32r(nk1v.z); u.w = tf32r(nk1v.w);
            *(uint4*)&Ksn[kr1 * 36 + ksg * 4] = u;
            KsTn[(ksg*4 + 0) * 68 + kr1] = __uint_as_float(u.x);
            KsTn[(ksg*4 + 1) * 68 + kr1] = __uint_as_float(u.y);
            KsTn[(ksg*4 + 2) * 68 + kr1] = __uint_as_float(u.z);
            KsTn[(ksg*4 + 3) * 68 + kr1] = __uint_as_float(u.w);
        }
    }

    // quad-reduce denominators
    den0 += __shfl_xor_sync(0xffffffffu, den0, 1);
    den0 += __shfl_xor_sync(0xffffffffu, den0, 2);
    den1 += __shfl_xor_sync(0xffffffffu, den1, 1);
    den1 += __shfl_xor_sync(0xffffffffu, den1, 2);

    // ---- write unnormalized partials ----
    float* on = g_on + (size_t)split * B_ * S_ * C_;
    float* ob0 = on + ((size_t)b * S_ + row0) * C_ + h * HD_;
    float* ob1 = on + ((size_t)b * S_ + row1) * C_ + h * HD_;
    #pragma unroll
    for (int nt2 = 0; nt2 < 4; nt2++) {
        if (v0) {
            float2 r; r.x = o[nt2][0]; r.y = o[nt2][1];
            *(float2*)(ob0 + nt2 * 8 + 2 * c) = r;
        }
        if (v1) {
            float2 r; r.x = o[nt2][2]; r.y = o[nt2][3];
            *(float2*)(ob1 + nt2 * 8 + 2 * c) = r;
        }
    }
    if (c == 0) {
        float* dn = g_dn + (size_t)split * B_ * H_ * S_ + ((size_t)b * H_ + h) * S_;
        if (v0) dn[row0] = den0;
        if (v1) dn[row1] = den1;
    }
}

// ---------------------------------------------------------------------------
// Finalize for query tokens (s < QN): g_att = (O0+O1)/(d0+d1)
// ---------------------------------------------------------------------------
__global__ __launch_bounds__(256) void finalize_q_kernel()
{
    const int s = blockIdx.x, b = blockIdx.y, c = threadIdx.x;
    const int h = c >> 5;
    const size_t di = ((size_t)b * H_ + h) * S_ + s;
    const float den = g_dn[di] + g_dn[(size_t)B_ * H_ * S_ + di];
    const size_t oi = ((size_t)b * S_ + s) * C_ + c;
    g_att[oi] = (g_on[oi] + g_on[(size_t)B_ * S_ * C_ + oi]) / den;
}

// ---------------------------------------------------------------------------
// Fused finalize + LEPE for image tokens (s >= QN):
// g_att = (O0+O1)/(d0+d1) + dwconv5x5(v) + lepe_bias
// ---------------------------------------------------------------------------
__global__ __launch_bounds__(256) void lepe_fin_kernel(
    const float* __restrict__ lw, const float* __restrict__ lb)
{
    __shared__ float dsh[8];
    const int p = blockIdx.x;            // 0..3135
    const int b = blockIdx.y;
    const int c = threadIdx.x;
    const int s = QN_ + p;

    if (c < 8) {
        const size_t di = ((size_t)b * H_ + c) * S_ + s;
        dsh[c] = g_dn[di] + g_dn[(size_t)B_ * H_ * S_ + di];
    }
    __syncthreads();

    const size_t oi = ((size_t)b * S_ + s) * C_ + c;
    const float fin = (g_on[oi] + g_on[(size_t)B_ * S_ * C_ + oi]) / dsh[c >> 5];

    const int i = p / IMW_, j = p % IMW_;
    float acc = lb[c];
    #pragma unroll
    for (int u = 0; u < 5; u++) {
        const int ii = i + u - 2;
        if ((unsigned)ii >= IMH_) continue;
        const float* vrow = g_v + ((size_t)b * S_ + QN_ + ii * IMW_ + j - 2) * C_ + c;
        const float* wrow = lw + (u * 5) * C_ + c;
        #pragma unroll
        for (int v = 0; v < 5; v++) {
            const int jj = j + v - 2;
            if ((unsigned)jj < IMW_)
                acc += vrow[(size_t)v * C_] * wrow[(size_t)v * C_];
        }
    }
    g_att[oi] = fin + acc;
}

// ---------------------------------------------------------------------------
extern "C" void kernel_launch(void* const* d_in, const int* in_sizes, int n_in,
                              void* d_out, int out_size)
{
    const float* x    = (const float*)d_in[0];
    const float* mask = (const float*)d_in[1];
    const float* wq   = (const float*)d_in[2];
    const float* bq   = (const float*)d_in[3];
    const float* wk   = (const float*)d_in[4];
    const float* bk   = (const float*)d_in[5];
    const float* wv   = (const float*)d_in[6];
    const float* bv   = (const float*)d_in[7];
    const float* lw   = (const float*)d_in[8];
    const float* lb   = (const float*)d_in[9];
    const float* wo   = (const float*)d_in[10];
    const float* bo   = (const float*)d_in[11];
    float* out = (float*)d_out;

    const int M = B_ * S_;                       // 6288
    dim3 gqkv((M + 127) / 128, C_ / 64, 3);      // 50 x 4 x 3
    dim3 go((M + 127) / 128, C_ / 64);           // 50 x 4

    static int smem_set = 0;
    if (!smem_set) {
        cudaFuncSetAttribute(attn_mma_kernel,
                             cudaFuncAttributeMaxDynamicSharedMemorySize, SMEM_ATTN);
        smem_set = 1;
    }

    qkv_gemm_kernel<<<gqkv, 256>>>(x, wq, bq, wk, bk, wv, bv);

    attn_mma_kernel<<<dim3((S_ + 127) / 128, H_, B_ * 2), 256, SMEM_ATTN>>>(mask);

    finalize_q_kernel<<<dim3(QN_, B_), 256>>>();
    lepe_fin_kernel<<<dim3(IMH_ * IMW_, B_), 256>>>(lw, lb);

    out_gemm_kernel<<<go, 256>>>(wo, bo, out);
}